// round 4
// baseline (speedup 1.0000x reference)
#include <cuda_runtime.h>
#include <cstdint>

#define N_SRC_MAX 100000
#define N_DST_MAX 50000
#define E_MAX     1250000
#define F         64
#define CAP       96     // per-dst bucket capacity (max deg ~48 for this dist)

// Scratch (device globals; no allocation allowed)
__device__ float  g_neigh[N_DST_MAX * F];     // segment-sum result
__device__ float2 g_huc[N_SRC_MAX];           // {hu, norm_deg_src/q/E}
__device__ float2 g_hvd[N_DST_MAX];           // {hv, norm_deg_dst}
__device__ int    g_cnt[N_DST_MAX];           // bucket cursors
__device__ int    g_srcbuf[N_DST_MAX * CAP];  // bucketed src ids

// ---------------------------------------------------------------------------
// Kernel 0: zero bucket counters
// ---------------------------------------------------------------------------
__global__ void zero_cnt_kernel(int n_dst) {
    int i = blockIdx.x * blockDim.x + threadIdx.x;
    if (i < n_dst) g_cnt[i] = 0;
}

// ---------------------------------------------------------------------------
// Kernel 1: per-node projections. One warp per node (src nodes first, then dst).
// ---------------------------------------------------------------------------
__global__ void node_proj_kernel(const float* __restrict__ nfs,
                                 const float* __restrict__ nfd,
                                 const float* __restrict__ nds,
                                 const float* __restrict__ ndd,
                                 const float* __restrict__ q,
                                 const float* __restrict__ sw,  // [64,2] row-major
                                 int n_src, int n_dst, float inv_e) {
    int warp = (blockIdx.x * blockDim.x + threadIdx.x) >> 5;
    int lane = threadIdx.x & 31;
    if (warp < n_src) {
        int i = warp;
        float v = nfs[i * F + lane]      * sw[lane * 2]
                + nfs[i * F + 32 + lane] * sw[(lane + 32) * 2];
        #pragma unroll
        for (int o = 16; o; o >>= 1) v += __shfl_xor_sync(0xFFFFFFFFu, v, o);
        if (lane == 0) {
            g_huc[i] = make_float2(v, nds[i] / q[i] * inv_e);
        }
    } else if (warp < n_src + n_dst) {
        int i = warp - n_src;
        float v = nfd[i * F + lane]      * sw[lane * 2 + 1]
                + nfd[i * F + 32 + lane] * sw[(lane + 32) * 2 + 1];
        #pragma unroll
        for (int o = 16; o; o >>= 1) v += __shfl_xor_sync(0xFFFFFFFFu, v, o);
        if (lane == 0) g_hvd[i] = make_float2(v, ndd[i]);
    }
}

// ---------------------------------------------------------------------------
// Kernel 2: bucket fill. One thread per edge: bump cursor, store src id.
// ---------------------------------------------------------------------------
__global__ void fill_kernel(const int* __restrict__ src_idx,
                            const int* __restrict__ dst_idx,
                            int n_edges) {
    int e = blockIdx.x * blockDim.x + threadIdx.x;
    if (e < n_edges) {
        int s = src_idx[e];
        int d = dst_idx[e];
        int p = atomicAdd(&g_cnt[d], 1);
        if (p < CAP) g_srcbuf[d * CAP + p] = s;
    }
}

// ---------------------------------------------------------------------------
// Kernel 3: SpMM. One warp per dst row; accumulate in registers (float2/lane),
// single coalesced write. att recomputed in-loop (hvd loaded once per row).
// ---------------------------------------------------------------------------
__global__ void spmm_kernel(const float* __restrict__ hidden, int n_dst) {
    int warp = (blockIdx.x * blockDim.x + threadIdx.x) >> 5;
    int lane = threadIdx.x & 31;
    if (warp >= n_dst) return;
    int d = warp;

    int cnt = g_cnt[d];
    if (cnt > CAP) cnt = CAP;
    const int* sb = &g_srcbuf[d * CAP];
    const float2* hid2 = (const float2*)hidden;
    float2 vd = g_hvd[d];

    float2 acc = make_float2(0.f, 0.f);
    int i = 0;
    for (; i + 2 <= cnt; i += 2) {
        int s0 = sb[i];
        int s1 = sb[i + 1];
        float2 uc0 = g_huc[s0];
        float2 uc1 = g_huc[s1];
        float2 h0 = hid2[s0 * (F / 2) + lane];
        float2 h1 = hid2[s1 * (F / 2) + lane];
        float a0 = uc0.y * vd.y * (fmaxf(uc0.x + vd.x, 0.f) + 0.1f);
        float a1 = uc1.y * vd.y * (fmaxf(uc1.x + vd.x, 0.f) + 0.1f);
        acc.x += h0.x * a0 + h1.x * a1;
        acc.y += h0.y * a0 + h1.y * a1;
    }
    if (i < cnt) {
        int s0 = sb[i];
        float2 uc0 = g_huc[s0];
        float2 h0 = hid2[s0 * (F / 2) + lane];
        float a0 = uc0.y * vd.y * (fmaxf(uc0.x + vd.x, 0.f) + 0.1f);
        acc.x += h0.x * a0;
        acc.y += h0.y * a0;
    }
    ((float2*)g_neigh)[d * (F / 2) + lane] = acc;
}

// ---------------------------------------------------------------------------
// Kernel 4: FC epilogue. rst = neigh @ fc_weight^T + fc_bias
// 64x64 output tile per block, 256 threads, 4x4 register blocking.
// ---------------------------------------------------------------------------
__global__ void __launch_bounds__(256) fc_kernel(
        const float* __restrict__ fcw,   // [64,64] row-major: fcw[c][k]
        const float* __restrict__ bias,
        float* __restrict__ out, int n_dst) {
    __shared__ float fwT[F * F];          // fwT[k*64 + c] = fcw[c*64 + k]
    __shared__ float ns[F * F];           // ns[r*64 + k]
    int tid = threadIdx.x;
    int row0 = blockIdx.x * 64;

    #pragma unroll
    for (int j = tid; j < F * F; j += 256)
        fwT[(j & 63) * F + (j >> 6)] = fcw[j];
    #pragma unroll
    for (int j = tid; j < F * F / 4; j += 256) {
        int r = j >> 4;
        int o = j & 15;
        int gr = row0 + r;
        float4 v = (gr < n_dst) ? ((const float4*)g_neigh)[gr * 16 + o]
                                : make_float4(0.f, 0.f, 0.f, 0.f);
        ((float4*)ns)[j] = v;
    }
    __syncthreads();

    int tx = tid & 15;
    int ty = tid >> 4;
    int c0 = tx * 4;
    int r0 = ty * 4;

    float4 b4 = *(const float4*)&bias[c0];
    float4 acc[4];
    #pragma unroll
    for (int i = 0; i < 4; i++) acc[i] = b4;

    #pragma unroll
    for (int k4 = 0; k4 < F; k4 += 4) {
        float4 a[4], w[4];
        #pragma unroll
        for (int i = 0; i < 4; i++)
            a[i] = *(const float4*)&ns[(r0 + i) * F + k4];
        #pragma unroll
        for (int kk = 0; kk < 4; kk++)
            w[kk] = *(const float4*)&fwT[(k4 + kk) * F + c0];
        #pragma unroll
        for (int i = 0; i < 4; i++) {
            acc[i].x += a[i].x * w[0].x + a[i].y * w[1].x + a[i].z * w[2].x + a[i].w * w[3].x;
            acc[i].y += a[i].x * w[0].y + a[i].y * w[1].y + a[i].z * w[2].y + a[i].w * w[3].y;
            acc[i].z += a[i].x * w[0].z + a[i].y * w[1].z + a[i].z * w[2].z + a[i].w * w[3].z;
            acc[i].w += a[i].x * w[0].w + a[i].y * w[1].w + a[i].z * w[2].w + a[i].w * w[3].w;
        }
    }

    #pragma unroll
    for (int i = 0; i < 4; i++) {
        int r = row0 + r0 + i;
        if (r < n_dst)
            *(float4*)&out[r * F + c0] = acc[i];
    }
}

// ---------------------------------------------------------------------------
// Launch
// ---------------------------------------------------------------------------
extern "C" void kernel_launch(void* const* d_in, const int* in_sizes, int n_in,
                              void* d_out, int out_size) {
    const float* hidden_feat   = (const float*)d_in[0];
    const float* node_feat_src = (const float*)d_in[1];
    const float* node_feat_dst = (const float*)d_in[2];
    const float* norm_deg_src  = (const float*)d_in[3];
    const float* norm_deg_dst  = (const float*)d_in[4];
    const float* q_probs       = (const float*)d_in[5];
    const float* sample_w      = (const float*)d_in[6];
    const float* fc_weight     = (const float*)d_in[7];
    const float* fc_bias       = (const float*)d_in[8];
    const int*   src_idx       = (const int*)d_in[9];
    const int*   dst_idx       = (const int*)d_in[10];

    int n_src   = in_sizes[3];
    int n_dst   = in_sizes[4];
    int n_edges = in_sizes[9];
    if (n_src > N_SRC_MAX) n_src = N_SRC_MAX;
    if (n_dst > N_DST_MAX) n_dst = N_DST_MAX;
    if (n_edges > E_MAX)   n_edges = E_MAX;

    float* out = (float*)d_out;
    float inv_e = 1.0f / (float)n_edges;

    // 0: zero bucket counters
    zero_cnt_kernel<<<(n_dst + 255) / 256, 256>>>(n_dst);
    // 1: node projections (one warp per node)
    {
        int warps = n_src + n_dst;
        int blocks = (warps * 32 + 255) / 256;
        node_proj_kernel<<<blocks, 256>>>(node_feat_src, node_feat_dst,
                                          norm_deg_src, norm_deg_dst, q_probs,
                                          sample_w, n_src, n_dst, inv_e);
    }
    // 2: bucket fill
    fill_kernel<<<(n_edges + 255) / 256, 256>>>(src_idx, dst_idx, n_edges);
    // 3: SpMM (one warp per dst row)
    {
        int warps = n_dst;
        int blocks = (warps * 32 + 255) / 256;
        spmm_kernel<<<blocks, 256>>>(hidden_feat, n_dst);
    }
    // 4: FC epilogue (64 rows per block)
    fc_kernel<<<(n_dst + 63) / 64, 256>>>(fc_weight, fc_bias, out, n_dst);
}

// round 5
// speedup vs baseline: 1.1470x; 1.1470x over previous
#include <cuda_runtime.h>
#include <cstdint>

#define N_SRC_MAX 100000
#define N_DST_MAX 50000
#define E_MAX     1250000
#define F         64
#define CAP       96     // per-dst bucket capacity (max deg ~48 for this dist)

// Scratch (device globals; no allocation allowed)
__device__ float  g_neigh[N_DST_MAX * F];     // segment-sum result
__device__ float2 g_huc[N_SRC_MAX];           // {hu, norm_deg_src/q/E}
__device__ float2 g_hvd[N_DST_MAX];           // {hv, norm_deg_dst}
__device__ int    g_cnt[N_DST_MAX];           // bucket cursors
__device__ int    g_srcbuf[N_DST_MAX * CAP];  // bucketed src ids

// ---------------------------------------------------------------------------
// Kernel 0: zero bucket counters
// ---------------------------------------------------------------------------
__global__ void zero_cnt_kernel(int n_dst) {
    int i = blockIdx.x * blockDim.x + threadIdx.x;
    if (i < n_dst) g_cnt[i] = 0;
}

// ---------------------------------------------------------------------------
// Kernel 1: per-node projections. One warp per node (src nodes first, then dst).
// ---------------------------------------------------------------------------
__global__ void node_proj_kernel(const float* __restrict__ nfs,
                                 const float* __restrict__ nfd,
                                 const float* __restrict__ nds,
                                 const float* __restrict__ ndd,
                                 const float* __restrict__ q,
                                 const float* __restrict__ sw,  // [64,2] row-major
                                 int n_src, int n_dst, float inv_e) {
    int warp = (blockIdx.x * blockDim.x + threadIdx.x) >> 5;
    int lane = threadIdx.x & 31;
    if (warp < n_src) {
        int i = warp;
        float v = nfs[i * F + lane]      * sw[lane * 2]
                + nfs[i * F + 32 + lane] * sw[(lane + 32) * 2];
        #pragma unroll
        for (int o = 16; o; o >>= 1) v += __shfl_xor_sync(0xFFFFFFFFu, v, o);
        if (lane == 0) {
            g_huc[i] = make_float2(v, nds[i] / q[i] * inv_e);
        }
    } else if (warp < n_src + n_dst) {
        int i = warp - n_src;
        float v = nfd[i * F + lane]      * sw[lane * 2 + 1]
                + nfd[i * F + 32 + lane] * sw[(lane + 32) * 2 + 1];
        #pragma unroll
        for (int o = 16; o; o >>= 1) v += __shfl_xor_sync(0xFFFFFFFFu, v, o);
        if (lane == 0) g_hvd[i] = make_float2(v, ndd[i]);
    }
}

// ---------------------------------------------------------------------------
// Kernel 2: bucket fill. One thread per edge: bump cursor, store src id.
// ---------------------------------------------------------------------------
__global__ void fill_kernel(const int* __restrict__ src_idx,
                            const int* __restrict__ dst_idx,
                            int n_edges) {
    int e = blockIdx.x * blockDim.x + threadIdx.x;
    if (e < n_edges) {
        int s = src_idx[e];
        int d = dst_idx[e];
        int p = atomicAdd(&g_cnt[d], 1);
        if (p < CAP) g_srcbuf[d * CAP + p] = s;
    }
}

// ---------------------------------------------------------------------------
// Kernel 3: SpMM. One warp per dst row; accumulate in registers (float2/lane),
// single coalesced write. Unroll x4 with int4 id load + batched gathers (MLP~9).
// ---------------------------------------------------------------------------
__global__ void __launch_bounds__(256) spmm_kernel(
        const float* __restrict__ hidden, int n_dst) {
    int warp = (blockIdx.x * blockDim.x + threadIdx.x) >> 5;
    int lane = threadIdx.x & 31;
    if (warp >= n_dst) return;
    int d = warp;

    int cnt = g_cnt[d];
    if (cnt > CAP) cnt = CAP;
    const int* sb = &g_srcbuf[d * CAP];
    const float2* hid2 = (const float2*)hidden;
    float2 vd = g_hvd[d];

    float2 acc = make_float2(0.f, 0.f);
    int i = 0;
    for (; i + 4 <= cnt; i += 4) {
        int4 s4 = *(const int4*)&sb[i];      // 16B-aligned (CAP*4=384B, i%4==0)
        float2 uc0 = __ldg(&g_huc[s4.x]);
        float2 uc1 = __ldg(&g_huc[s4.y]);
        float2 uc2 = __ldg(&g_huc[s4.z]);
        float2 uc3 = __ldg(&g_huc[s4.w]);
        float2 h0 = __ldg(&hid2[s4.x * (F / 2) + lane]);
        float2 h1 = __ldg(&hid2[s4.y * (F / 2) + lane]);
        float2 h2 = __ldg(&hid2[s4.z * (F / 2) + lane]);
        float2 h3 = __ldg(&hid2[s4.w * (F / 2) + lane]);
        float a0 = uc0.y * vd.y * (fmaxf(uc0.x + vd.x, 0.f) + 0.1f);
        float a1 = uc1.y * vd.y * (fmaxf(uc1.x + vd.x, 0.f) + 0.1f);
        float a2 = uc2.y * vd.y * (fmaxf(uc2.x + vd.x, 0.f) + 0.1f);
        float a3 = uc3.y * vd.y * (fmaxf(uc3.x + vd.x, 0.f) + 0.1f);
        acc.x += h0.x * a0 + h1.x * a1 + h2.x * a2 + h3.x * a3;
        acc.y += h0.y * a0 + h1.y * a1 + h2.y * a2 + h3.y * a3;
    }
    for (; i < cnt; i++) {
        int s0 = sb[i];
        float2 uc0 = __ldg(&g_huc[s0]);
        float2 h0 = __ldg(&hid2[s0 * (F / 2) + lane]);
        float a0 = uc0.y * vd.y * (fmaxf(uc0.x + vd.x, 0.f) + 0.1f);
        acc.x += h0.x * a0;
        acc.y += h0.y * a0;
    }
    ((float2*)g_neigh)[d * (F / 2) + lane] = acc;
}

// ---------------------------------------------------------------------------
// Kernel 4: FC epilogue. rst = neigh @ fc_weight^T + fc_bias
// 128x64 output tile per block, 256 threads, 8x4 register blocking:
// per k4-step 12 LDS.128 feed 128 FMA.
// ---------------------------------------------------------------------------
#define FC_TILE_R 128
__global__ void __launch_bounds__(256) fc_kernel(
        const float* __restrict__ fcw,   // [64,64] row-major: fcw[c][k]
        const float* __restrict__ bias,
        float* __restrict__ out, int n_dst) {
    __shared__ float fwT[F * F];             // fwT[k*64 + c] = fcw[c*64 + k]
    __shared__ float ns[FC_TILE_R * F];      // ns[r*64 + k]
    int tid = threadIdx.x;
    int row0 = blockIdx.x * FC_TILE_R;

    #pragma unroll
    for (int j = tid; j < F * F; j += 256)
        fwT[(j & 63) * F + (j >> 6)] = fcw[j];
    #pragma unroll
    for (int j = tid; j < FC_TILE_R * F / 4; j += 256) {
        int r = j >> 4;                      // 16 float4 per row
        int o = j & 15;
        int gr = row0 + r;
        float4 v = (gr < n_dst) ? ((const float4*)g_neigh)[gr * 16 + o]
                                : make_float4(0.f, 0.f, 0.f, 0.f);
        ((float4*)ns)[j] = v;
    }
    __syncthreads();

    int tx = tid & 15;          // col group: c0 = tx*4
    int ty = tid >> 4;          // 0..15; rows ty + 16*j, j=0..7
    int c0 = tx * 4;

    float4 b4 = *(const float4*)&bias[c0];
    float4 acc[8];
    #pragma unroll
    for (int j = 0; j < 8; j++) acc[j] = b4;

    #pragma unroll
    for (int k4 = 0; k4 < F; k4 += 4) {
        float4 w[4];
        #pragma unroll
        for (int kk = 0; kk < 4; kk++)
            w[kk] = *(const float4*)&fwT[(k4 + kk) * F + c0];
        #pragma unroll
        for (int j = 0; j < 8; j++) {
            float4 a = *(const float4*)&ns[(ty + 16 * j) * F + k4];
            acc[j].x += a.x * w[0].x + a.y * w[1].x + a.z * w[2].x + a.w * w[3].x;
            acc[j].y += a.x * w[0].y + a.y * w[1].y + a.z * w[2].y + a.w * w[3].y;
            acc[j].z += a.x * w[0].z + a.y * w[1].z + a.z * w[2].z + a.w * w[3].z;
            acc[j].w += a.x * w[0].w + a.y * w[1].w + a.z * w[2].w + a.w * w[3].w;
        }
    }

    #pragma unroll
    for (int j = 0; j < 8; j++) {
        int r = row0 + ty + 16 * j;
        if (r < n_dst)
            *(float4*)&out[r * F + c0] = acc[j];
    }
}

// ---------------------------------------------------------------------------
// Launch
// ---------------------------------------------------------------------------
extern "C" void kernel_launch(void* const* d_in, const int* in_sizes, int n_in,
                              void* d_out, int out_size) {
    const float* hidden_feat   = (const float*)d_in[0];
    const float* node_feat_src = (const float*)d_in[1];
    const float* node_feat_dst = (const float*)d_in[2];
    const float* norm_deg_src  = (const float*)d_in[3];
    const float* norm_deg_dst  = (const float*)d_in[4];
    const float* q_probs       = (const float*)d_in[5];
    const float* sample_w      = (const float*)d_in[6];
    const float* fc_weight     = (const float*)d_in[7];
    const float* fc_bias       = (const float*)d_in[8];
    const int*   src_idx       = (const int*)d_in[9];
    const int*   dst_idx       = (const int*)d_in[10];

    int n_src   = in_sizes[3];
    int n_dst   = in_sizes[4];
    int n_edges = in_sizes[9];
    if (n_src > N_SRC_MAX) n_src = N_SRC_MAX;
    if (n_dst > N_DST_MAX) n_dst = N_DST_MAX;
    if (n_edges > E_MAX)   n_edges = E_MAX;

    float* out = (float*)d_out;
    float inv_e = 1.0f / (float)n_edges;

    // 0: zero bucket counters
    zero_cnt_kernel<<<(n_dst + 255) / 256, 256>>>(n_dst);
    // 1: node projections (one warp per node)
    {
        int warps = n_src + n_dst;
        int blocks = (warps * 32 + 255) / 256;
        node_proj_kernel<<<blocks, 256>>>(node_feat_src, node_feat_dst,
                                          norm_deg_src, norm_deg_dst, q_probs,
                                          sample_w, n_src, n_dst, inv_e);
    }
    // 2: bucket fill
    fill_kernel<<<(n_edges + 255) / 256, 256>>>(src_idx, dst_idx, n_edges);
    // 3: SpMM (one warp per dst row, x4 unroll)
    {
        int warps = n_dst;
        int blocks = (warps * 32 + 255) / 256;
        spmm_kernel<<<blocks, 256>>>(hidden_feat, n_dst);
    }
    // 4: FC epilogue (128 rows per block, 8x4 blocking)
    fc_kernel<<<(n_dst + FC_TILE_R - 1) / FC_TILE_R, 256>>>(fc_weight, fc_bias,
                                                            out, n_dst);
}